// round 11
// baseline (speedup 1.0000x reference)
#include <cuda_runtime.h>
#include <cuda_bf16.h>
#include <cstdint>

#define M_TOT 8192
#define D_DIM 2048
#define O_DIM 2048
#define E_NUM 8
#define R_DIM 16
#define KLORA 128
#define K_TOT 2176          // D_DIM + KLORA

// ---------------- scratch (bf16 stored as ushort) ----------------
__device__ float g_rw[M_TOT * E_NUM];
__device__ unsigned short g_Ahi[(size_t)M_TOT * K_TOT];   // [X|Z] hi, 35.7 MB
__device__ unsigned short g_Alo[(size_t)M_TOT * K_TOT];
__device__ unsigned short g_Bhi[(size_t)O_DIM * K_TOT];   // [W|Bcat] hi, 8.9 MB
__device__ unsigned short g_Blo[(size_t)O_DIM * K_TOT];
__device__ unsigned short g_Achi[(size_t)KLORA * D_DIM];  // Acat^T [128][2048]
__device__ unsigned short g_Aclo[(size_t)KLORA * D_DIM];

// ---------------- helpers ----------------
__device__ __forceinline__ uint32_t s2u(const void* p) {
    uint32_t a;
    asm("{ .reg .u64 t; cvta.to.shared.u64 t, %1; cvt.u32.u64 %0, t; }"
        : "=r"(a) : "l"(p));
    return a;
}
__device__ __forceinline__ void cp16(uint32_t dst, const void* src) {
    asm volatile("cp.async.cg.shared.global [%0], [%1], 16;" :: "r"(dst), "l"(src));
}
#define CP_COMMIT() asm volatile("cp.async.commit_group;" ::: "memory")
#define CP_WAIT1()  asm volatile("cp.async.wait_group 1;" ::: "memory")

__device__ __forceinline__ void ldm_x4(uint32_t* r, uint32_t addr) {
    asm volatile("ldmatrix.sync.aligned.m8n8.x4.shared.b16 {%0,%1,%2,%3}, [%4];"
        : "=r"(r[0]), "=r"(r[1]), "=r"(r[2]), "=r"(r[3]) : "r"(addr));
}
__device__ __forceinline__ void mma_bf16(float* d, const uint32_t* a,
                                         uint32_t b0, uint32_t b1) {
    asm volatile(
        "mma.sync.aligned.m16n8k16.row.col.f32.bf16.bf16.f32 "
        "{%0,%1,%2,%3}, {%4,%5,%6,%7}, {%8,%9}, {%0,%1,%2,%3};"
        : "+f"(d[0]), "+f"(d[1]), "+f"(d[2]), "+f"(d[3])
        : "r"(a[0]), "r"(a[1]), "r"(a[2]), "r"(a[3]), "r"(b0), "r"(b1));
}
__device__ __forceinline__ unsigned short bf_hi(float v) {
    return __bfloat16_as_ushort(__float2bfloat16_rn(v));
}
__device__ __forceinline__ unsigned short bf_lo(float v) {
    float h = __bfloat162float(__float2bfloat16_rn(v));
    return __bfloat16_as_ushort(__float2bfloat16_rn(v - h));
}

// swizzled byte offset within a tile: row, 16B-chunk byte offset (0..127)
__device__ __forceinline__ uint32_t tswz(int row, int cbyte) {
    return (uint32_t)(row * 128 + (cbyte ^ ((row & 7) << 4)));
}

// ---------------------------------------------------------------------------
// Prep 1: x -> bf16 hi/lo splits into g_Ahi/g_Alo cols [0,2048);
// router logits + top-2 softmax -> g_rw. 32 rows per block, Wr cached in smem.
// ---------------------------------------------------------------------------
__global__ __launch_bounds__(256) void prep_rs_kernel(
    const float* __restrict__ x, const float* __restrict__ Wr)
{
    extern __shared__ float psm[];
    float* wr_s = psm;            // 16384 floats = 64KB
    float* sred = psm + 16384;    // 64 floats
    const int tid = threadIdx.x;
    const int lane = tid & 31, warp = tid >> 5;

    for (int i = tid; i < 4096; i += 256)
        reinterpret_cast<float4*>(wr_s)[i] = reinterpret_cast<const float4*>(Wr)[i];
    __syncthreads();

    const int m0 = blockIdx.x * 32;
    for (int r = 0; r < 32; r++) {
        const int m = m0 + r;
        const float4* xr = reinterpret_cast<const float4*>(x + (size_t)m * D_DIM);
        float acc[E_NUM];
#pragma unroll
        for (int e = 0; e < E_NUM; e++) acc[e] = 0.f;

#pragma unroll
        for (int it = 0; it < 2; it++) {
            int i = tid + it * 256;
            float4 xv = xr[i];
            ushort4 hv, lv;
            hv.x = bf_hi(xv.x); lv.x = bf_lo(xv.x);
            hv.y = bf_hi(xv.y); lv.y = bf_lo(xv.y);
            hv.z = bf_hi(xv.z); lv.z = bf_lo(xv.z);
            hv.w = bf_hi(xv.w); lv.w = bf_lo(xv.w);
            *reinterpret_cast<ushort4*>(g_Ahi + (size_t)m * K_TOT + i * 4) = hv;
            *reinterpret_cast<ushort4*>(g_Alo + (size_t)m * K_TOT + i * 4) = lv;
#pragma unroll
            for (int e = 0; e < E_NUM; e++) {
                float4 wv = reinterpret_cast<const float4*>(wr_s + e * D_DIM)[i];
                acc[e] += xv.x * wv.x + xv.y * wv.y + xv.z * wv.z + xv.w * wv.w;
            }
        }
#pragma unroll
        for (int e = 0; e < E_NUM; e++) {
            float v = acc[e];
#pragma unroll
            for (int off = 16; off > 0; off >>= 1)
                v += __shfl_down_sync(0xffffffffu, v, off);
            if (lane == 0) sred[e * 8 + warp] = v;
        }
        __syncthreads();
        if (tid == 0) {
            float lg[E_NUM];
#pragma unroll
            for (int e = 0; e < E_NUM; e++) {
                float s = 0.f;
#pragma unroll
                for (int w = 0; w < 8; w++) s += sred[e * 8 + w];
                lg[e] = s;
            }
            int i1 = 0;
#pragma unroll
            for (int e = 1; e < E_NUM; e++) if (lg[e] > lg[i1]) i1 = e;
            int i2 = -1;
#pragma unroll
            for (int e = 0; e < E_NUM; e++) {
                if (e == i1) continue;
                if (i2 < 0 || lg[e] > lg[i2]) i2 = e;
            }
            float e2 = __expf(lg[i2] - lg[i1]);
            float inv = 1.0f / (1.0f + e2);
            float* dst = g_rw + (size_t)m * E_NUM;
#pragma unroll
            for (int e = 0; e < E_NUM; e++) dst[e] = 0.f;
            dst[i1] = inv;
            dst[i2] = e2 * inv;
        }
        __syncthreads();
    }
}

// ---------------------------------------------------------------------------
// Prep 2: W -> g_Bhi/g_Blo cols [0,2048); Bexp -> cols [2048,2176).
// ---------------------------------------------------------------------------
__global__ __launch_bounds__(256) void split_wb_kernel(
    const float* __restrict__ W, const float* __restrict__ Bexp)
{
    const int o = blockIdx.x;
    const int tid = threadIdx.x;
    const float4* src = reinterpret_cast<const float4*>(W + (size_t)o * D_DIM);
    for (int i = tid; i < D_DIM / 4; i += 256) {
        float4 v = src[i];
        ushort4 hv, lv;
        hv.x = bf_hi(v.x); lv.x = bf_lo(v.x);
        hv.y = bf_hi(v.y); lv.y = bf_lo(v.y);
        hv.z = bf_hi(v.z); lv.z = bf_lo(v.z);
        hv.w = bf_hi(v.w); lv.w = bf_lo(v.w);
        *reinterpret_cast<ushort4*>(g_Bhi + (size_t)o * K_TOT + i * 4) = hv;
        *reinterpret_cast<ushort4*>(g_Blo + (size_t)o * K_TOT + i * 4) = lv;
    }
    if (tid < KLORA) {
        float v = Bexp[(size_t)tid * O_DIM + o];
        g_Bhi[(size_t)o * K_TOT + D_DIM + tid] = bf_hi(v);
        g_Blo[(size_t)o * K_TOT + D_DIM + tid] = bf_lo(v);
    }
}

// ---------------------------------------------------------------------------
// Prep 3: Acat^T splits: g_Achi[n][k], n = e*16+r.
// ---------------------------------------------------------------------------
__global__ __launch_bounds__(256) void split_acat_kernel(const float* __restrict__ A)
{
    const int n = blockIdx.x;
    const int e = n >> 4, r = n & 15;
    const int tid = threadIdx.x;
    for (int k = tid; k < D_DIM; k += 256) {
        float v = A[(size_t)e * D_DIM * R_DIM + (size_t)k * R_DIM + r];
        g_Achi[(size_t)n * D_DIM + k] = bf_hi(v);
        g_Aclo[(size_t)n * D_DIM + k] = bf_lo(v);
    }
}

// ---------------------------------------------------------------------------
// zgemm (fused 3-pass): Z = (X @ Acat) * rw -> bf16 splits, cols [2048,2176).
// Tile 64(M) x 128(N), BK=64, 3 stages. Stage = Ahi 8K | Alo 8K | Bh 16K | Bl 16K.
// 8 warps: wm = warp&1, wn = warp>>1; warp tile 32x32.  (unchanged from R9)
// ---------------------------------------------------------------------------
#define ZSTG 49152
#define ZSMEM (3 * ZSTG)

__global__ void __launch_bounds__(256, 1) zgemm_mma_kernel()
{
    extern __shared__ __align__(128) char smem[];
    const uint32_t sb = s2u(smem);
    const int tid = threadIdx.x;
    const int lane = tid & 31, warp = tid >> 5;
    const int wm = warp & 1, wn = warp >> 1;
    const int m0 = blockIdx.x * 64;

    float acc[2][4][4];
#pragma unroll
    for (int i = 0; i < 2; i++)
#pragma unroll
        for (int j = 0; j < 4; j++)
#pragma unroll
            for (int k = 0; k < 4; k++) acc[i][j][k] = 0.f;

    const int NT = 32;   // 2048 / 64
    const unsigned short* Ah = g_Ahi + (size_t)m0 * K_TOT;
    const unsigned short* Al = g_Alo + (size_t)m0 * K_TOT;

    auto load_chunk = [&](int t, int s) {
        const int k0 = t * 64;
        uint32_t Ab = sb + s * ZSTG;
#pragma unroll
        for (int j = 0; j < 2; j++) {               // A tiles: 64 rows * 8 chunks
            int idx = tid + j * 256;
            int row = idx >> 3, c = idx & 7;
            uint32_t off = tswz(row, c * 16);
            cp16(Ab + off,        Ah + (size_t)row * K_TOT + k0 + c * 8);
            cp16(Ab + 8192 + off, Al + (size_t)row * K_TOT + k0 + c * 8);
        }
#pragma unroll
        for (int j = 0; j < 4; j++) {               // B tiles: 128 rows * 8 chunks
            int idx = tid + j * 256;
            int row = idx >> 3, c = idx & 7;
            uint32_t off = tswz(row, c * 16);
            cp16(Ab + 16384 + off, g_Achi + (size_t)row * D_DIM + k0 + c * 8);
            cp16(Ab + 32768 + off, g_Aclo + (size_t)row * D_DIM + k0 + c * 8);
        }
    };

    load_chunk(0, 0); CP_COMMIT();
    load_chunk(1, 1); CP_COMMIT();

    for (int t = 0; t < NT; t++) {
        CP_WAIT1();
        __syncthreads();
        if (t + 2 < NT) load_chunk(t + 2, (t + 2) % 3);
        CP_COMMIT();
        const int s = t % 3;
        uint32_t Ab = sb + s * ZSTG;
#pragma unroll
        for (int kb = 0; kb < 4; kb++) {
            uint32_t ah[2][4], al[2][4], bh[2][4], bl[2][4];
            int colb = kb * 32 + (lane >> 4) * 16;
#pragma unroll
            for (int mt = 0; mt < 2; mt++) {
                uint32_t off = tswz(wm * 32 + mt * 16 + (lane & 15), colb);
                ldm_x4(ah[mt], Ab + off);
                ldm_x4(al[mt], Ab + 8192 + off);
            }
#pragma unroll
            for (int nt = 0; nt < 2; nt++) {
                uint32_t off = tswz(wn * 32 + nt * 16 + (lane & 15), colb);
                ldm_x4(bh[nt], Ab + 16384 + off);
                ldm_x4(bl[nt], Ab + 32768 + off);
            }
#pragma unroll
            for (int mt = 0; mt < 2; mt++)
#pragma unroll
                for (int ns = 0; ns < 4; ns++) {
                    uint32_t h0 = bh[ns >> 1][ns & 1], h1 = bh[ns >> 1][2 + (ns & 1)];
                    mma_bf16(acc[mt][ns], ah[mt], h0, h1);
                    mma_bf16(acc[mt][ns], al[mt], h0, h1);
                    mma_bf16(acc[mt][ns], ah[mt],
                             bl[ns >> 1][ns & 1], bl[ns >> 1][2 + (ns & 1)]);
                }
        }
        __syncthreads();
    }

    // epilogue: scale by router weight, split to bf16, store cols [2048,2176)
#pragma unroll
    for (int mt = 0; mt < 2; mt++)
#pragma unroll
        for (int ns = 0; ns < 4; ns++) {
            int m = m0 + wm * 32 + mt * 16 + (lane >> 2);
            int n = wn * 32 + ns * 8 + (lane & 3) * 2;
            int e = n >> 4;
            float w0 = g_rw[(size_t)m * E_NUM + e];
            float w1 = g_rw[(size_t)(m + 8) * E_NUM + e];
            float v0 = acc[mt][ns][0] * w0, v1 = acc[mt][ns][1] * w0;
            float v2 = acc[mt][ns][2] * w1, v3 = acc[mt][ns][3] * w1;
            ushort2 h0 = {bf_hi(v0), bf_hi(v1)}, l0 = {bf_lo(v0), bf_lo(v1)};
            ushort2 h1 = {bf_hi(v2), bf_hi(v3)}, l1 = {bf_lo(v2), bf_lo(v3)};
            *reinterpret_cast<ushort2*>(g_Ahi + (size_t)m * K_TOT + D_DIM + n) = h0;
            *reinterpret_cast<ushort2*>(g_Alo + (size_t)m * K_TOT + D_DIM + n) = l0;
            *reinterpret_cast<ushort2*>(g_Ahi + (size_t)(m + 8) * K_TOT + D_DIM + n) = h1;
            *reinterpret_cast<ushort2*>(g_Alo + (size_t)(m + 8) * K_TOT + D_DIM + n) = l1;
        }
}

// ---------------------------------------------------------------------------
// mgemm (fused 3-pass, 512 threads): out = [X|Z] @ [W|Bcat]^T + bias.
// Tile 128(M) x 128(N), BK=64, 3 stages (64KB each = 192KB). grid 1024.
// 16 warps: wm = warp&3 (4), wn = warp>>2 (4); warp tile 32x32.
// occ 16 warps/SM = 25% (vs 12.5% at 256 threads).
// ---------------------------------------------------------------------------
#define MSTG 65536
#define MSMEM (3 * MSTG)

__global__ void __launch_bounds__(512, 1) mgemm_mma_kernel(
    const float* __restrict__ bias, float* __restrict__ out)
{
    extern __shared__ __align__(128) char smem[];
    const uint32_t sb = s2u(smem);
    const int tid = threadIdx.x;
    const int lane = tid & 31, warp = tid >> 5;
    const int wm = warp & 3, wn = warp >> 2;
    const int n0 = blockIdx.x * 128;
    const int m0 = blockIdx.y * 128;

    float acc[2][4][4];
#pragma unroll
    for (int i = 0; i < 2; i++)
#pragma unroll
        for (int j = 0; j < 4; j++)
#pragma unroll
            for (int k = 0; k < 4; k++) acc[i][j][k] = 0.f;

    const int NT = 34;   // 2176 / 64
    const unsigned short* Ah = g_Ahi + (size_t)m0 * K_TOT;
    const unsigned short* Al = g_Alo + (size_t)m0 * K_TOT;
    const unsigned short* Bh = g_Bhi + (size_t)n0 * K_TOT;
    const unsigned short* Bl = g_Blo + (size_t)n0 * K_TOT;

    auto load_chunk = [&](int t, int s) {
        const int k0 = t * 64;
        uint32_t Ab = sb + s * MSTG;
#pragma unroll
        for (int j = 0; j < 2; j++) {               // 128 rows * 8 chunks per tile
            int idx = tid + j * 512;
            int row = idx >> 3, c = idx & 7;
            uint32_t off = tswz(row, c * 16);
            size_t go = (size_t)row * K_TOT + k0 + c * 8;
            cp16(Ab + off,         Ah + go);
            cp16(Ab + 16384 + off, Al + go);
            cp16(Ab + 32768 + off, Bh + go);
            cp16(Ab + 49152 + off, Bl + go);
        }
    };

    load_chunk(0, 0); CP_COMMIT();
    load_chunk(1, 1); CP_COMMIT();

    for (int t = 0; t < NT; t++) {
        CP_WAIT1();
        __syncthreads();
        if (t + 2 < NT) load_chunk(t + 2, (t + 2) % 3);
        CP_COMMIT();
        const int s = t % 3;
        uint32_t Ab = sb + s * MSTG;
#pragma unroll
        for (int kb = 0; kb < 4; kb++) {
            uint32_t ah[2][4], al[2][4], bh[2][4], bl[2][4];
            int colb = kb * 32 + (lane >> 4) * 16;
#pragma unroll
            for (int mt = 0; mt < 2; mt++) {
                uint32_t off = tswz(wm * 32 + mt * 16 + (lane & 15), colb);
                ldm_x4(ah[mt], Ab + off);
                ldm_x4(al[mt], Ab + 16384 + off);
            }
#pragma unroll
            for (int nt = 0; nt < 2; nt++) {
                uint32_t off = tswz(wn * 32 + nt * 16 + (lane & 15), colb);
                ldm_x4(bh[nt], Ab + 32768 + off);
                ldm_x4(bl[nt], Ab + 49152 + off);
            }
#pragma unroll
            for (int mt = 0; mt < 2; mt++)
#pragma unroll
                for (int ns = 0; ns < 4; ns++) {
                    uint32_t h0 = bh[ns >> 1][ns & 1], h1 = bh[ns >> 1][2 + (ns & 1)];
                    mma_bf16(acc[mt][ns], ah[mt], h0, h1);
                    mma_bf16(acc[mt][ns], al[mt], h0, h1);
                    mma_bf16(acc[mt][ns], ah[mt],
                             bl[ns >> 1][ns & 1], bl[ns >> 1][2 + (ns & 1)]);
                }
        }
        __syncthreads();
    }

    // epilogue: + bias, direct float2 stores
#pragma unroll
    for (int mt = 0; mt < 2; mt++)
#pragma unroll
        for (int ns = 0; ns < 4; ns++) {
            int m = m0 + wm * 32 + mt * 16 + (lane >> 2);
            int n = n0 + wn * 32 + ns * 8 + (lane & 3) * 2;
            float2 bv = *reinterpret_cast<const float2*>(bias + n);
            float2 v0 = {acc[mt][ns][0] + bv.x, acc[mt][ns][1] + bv.y};
            float2 v1 = {acc[mt][ns][2] + bv.x, acc[mt][ns][3] + bv.y};
            *reinterpret_cast<float2*>(out + (size_t)m * O_DIM + n) = v0;
            *reinterpret_cast<float2*>(out + (size_t)(m + 8) * O_DIM + n) = v1;
        }
}

// ---------------------------------------------------------------------------
extern "C" void kernel_launch(void* const* d_in, const int* in_sizes, int n_in,
                              void* d_out, int out_size)
{
    const float* x    = (const float*)d_in[0];
    const float* W    = (const float*)d_in[1];
    const float* bias = (const float*)d_in[2];
    const float* Wr   = (const float*)d_in[3];
    const float* A    = (const float*)d_in[4];
    const float* Bexp = (const float*)d_in[5];
    float* out = (float*)d_out;

    cudaFuncSetAttribute(prep_rs_kernel,
                         cudaFuncAttributeMaxDynamicSharedMemorySize, 66048);
    cudaFuncSetAttribute(zgemm_mma_kernel,
                         cudaFuncAttributeMaxDynamicSharedMemorySize, ZSMEM);
    cudaFuncSetAttribute(mgemm_mma_kernel,
                         cudaFuncAttributeMaxDynamicSharedMemorySize, MSMEM);

    prep_rs_kernel<<<M_TOT / 32, 256, 66048>>>(x, Wr);
    split_wb_kernel<<<O_DIM, 256>>>(W, Bexp);
    split_acat_kernel<<<KLORA, 256>>>(A);
    zgemm_mma_kernel<<<M_TOT / 64, 256, ZSMEM>>>();
    mgemm_mma_kernel<<<dim3(O_DIM / 128, M_TOT / 128), 512, MSMEM>>>(bias, out);
}

// round 13
// speedup vs baseline: 1.0743x; 1.0743x over previous
#include <cuda_runtime.h>
#include <cuda_bf16.h>
#include <cstdint>

#define M_TOT 8192
#define D_DIM 2048
#define O_DIM 2048
#define E_NUM 8
#define R_DIM 16
#define KLORA 128
#define K_TOT 2176          // D_DIM + KLORA

// ---------------- scratch (bf16 stored as ushort) ----------------
__device__ float g_rw[M_TOT * E_NUM];
__device__ unsigned short g_Ahi[(size_t)M_TOT * K_TOT];   // [X|Z] hi, 35.7 MB
__device__ unsigned short g_Alo[(size_t)M_TOT * K_TOT];
__device__ unsigned short g_Bhi[(size_t)O_DIM * K_TOT];   // [W|Bcat] hi, 8.9 MB
__device__ unsigned short g_Blo[(size_t)O_DIM * K_TOT];
__device__ unsigned short g_Achi[(size_t)KLORA * D_DIM];  // Acat^T [128][2048]
__device__ unsigned short g_Aclo[(size_t)KLORA * D_DIM];

// ---------------- helpers ----------------
__device__ __forceinline__ uint32_t s2u(const void* p) {
    uint32_t a;
    asm("{ .reg .u64 t; cvta.to.shared.u64 t, %1; cvt.u32.u64 %0, t; }"
        : "=r"(a) : "l"(p));
    return a;
}
__device__ __forceinline__ void cp16(uint32_t dst, const void* src) {
    asm volatile("cp.async.cg.shared.global [%0], [%1], 16;" :: "r"(dst), "l"(src));
}
#define CP_COMMIT() asm volatile("cp.async.commit_group;" ::: "memory")
#define CP_WAIT1()  asm volatile("cp.async.wait_group 1;" ::: "memory")

__device__ __forceinline__ void ldm_x4(uint32_t* r, uint32_t addr) {
    asm volatile("ldmatrix.sync.aligned.m8n8.x4.shared.b16 {%0,%1,%2,%3}, [%4];"
        : "=r"(r[0]), "=r"(r[1]), "=r"(r[2]), "=r"(r[3]) : "r"(addr));
}
__device__ __forceinline__ void mma_bf16(float* d, const uint32_t* a,
                                         uint32_t b0, uint32_t b1) {
    asm volatile(
        "mma.sync.aligned.m16n8k16.row.col.f32.bf16.bf16.f32 "
        "{%0,%1,%2,%3}, {%4,%5,%6,%7}, {%8,%9}, {%0,%1,%2,%3};"
        : "+f"(d[0]), "+f"(d[1]), "+f"(d[2]), "+f"(d[3])
        : "r"(a[0]), "r"(a[1]), "r"(a[2]), "r"(a[3]), "r"(b0), "r"(b1));
}
__device__ __forceinline__ unsigned short bf_hi(float v) {
    return __bfloat16_as_ushort(__float2bfloat16_rn(v));
}
__device__ __forceinline__ unsigned short bf_lo(float v) {
    float h = __bfloat162float(__float2bfloat16_rn(v));
    return __bfloat16_as_ushort(__float2bfloat16_rn(v - h));
}

// swizzled byte offset within a tile: row, 16B-chunk byte offset (0..127)
__device__ __forceinline__ uint32_t tswz(int row, int cbyte) {
    return (uint32_t)(row * 128 + (cbyte ^ ((row & 7) << 4)));
}

// ---------------------------------------------------------------------------
// Prep 1 (warp-parallel): x -> bf16 hi/lo splits into cols [0,2048);
// router top-2 softmax -> g_rw. 32 rows per block, 4 rows per warp,
// warp-local reductions only (no block barriers in the row loop).
// ---------------------------------------------------------------------------
__global__ __launch_bounds__(256) void prep_rs_kernel(
    const float* __restrict__ x, const float* __restrict__ Wr)
{
    extern __shared__ float wr_s[];   // 16384 floats = 64KB
    const int tid = threadIdx.x;
    const int lane = tid & 31, warp = tid >> 5;

    for (int i = tid; i < 4096; i += 256)
        reinterpret_cast<float4*>(wr_s)[i] = reinterpret_cast<const float4*>(Wr)[i];
    __syncthreads();
    const float4* wr4 = reinterpret_cast<const float4*>(wr_s);

    const int m0 = blockIdx.x * 32;
#pragma unroll
    for (int r = 0; r < 4; r++) {
        const int m = m0 + warp * 4 + r;
        const float4* xr = reinterpret_cast<const float4*>(x + (size_t)m * D_DIM);
        float acc[E_NUM];
#pragma unroll
        for (int e = 0; e < E_NUM; e++) acc[e] = 0.f;

#pragma unroll 4
        for (int i = lane; i < D_DIM / 4; i += 32) {
            float4 xv = xr[i];
            ushort4 hv, lv;
            hv.x = bf_hi(xv.x); lv.x = bf_lo(xv.x);
            hv.y = bf_hi(xv.y); lv.y = bf_lo(xv.y);
            hv.z = bf_hi(xv.z); lv.z = bf_lo(xv.z);
            hv.w = bf_hi(xv.w); lv.w = bf_lo(xv.w);
            *reinterpret_cast<ushort4*>(g_Ahi + (size_t)m * K_TOT + i * 4) = hv;
            *reinterpret_cast<ushort4*>(g_Alo + (size_t)m * K_TOT + i * 4) = lv;
#pragma unroll
            for (int e = 0; e < E_NUM; e++) {
                float4 wv = wr4[e * 512 + i];
                acc[e] += xv.x * wv.x + xv.y * wv.y + xv.z * wv.z + xv.w * wv.w;
            }
        }
#pragma unroll
        for (int e = 0; e < E_NUM; e++) {
#pragma unroll
            for (int off = 16; off > 0; off >>= 1)
                acc[e] += __shfl_xor_sync(0xffffffffu, acc[e], off);
        }
        if (lane == 0) {
            int i1 = 0;
#pragma unroll
            for (int e = 1; e < E_NUM; e++) if (acc[e] > acc[i1]) i1 = e;
            int i2 = -1;
#pragma unroll
            for (int e = 0; e < E_NUM; e++) {
                if (e == i1) continue;
                if (i2 < 0 || acc[e] > acc[i2]) i2 = e;
            }
            float e2 = __expf(acc[i2] - acc[i1]);
            float inv = 1.0f / (1.0f + e2);
            float out[E_NUM];
#pragma unroll
            for (int e = 0; e < E_NUM; e++) out[e] = 0.f;
            out[i1] = inv;
            out[i2] = e2 * inv;
            float4* dst = reinterpret_cast<float4*>(g_rw + (size_t)m * E_NUM);
            dst[0] = make_float4(out[0], out[1], out[2], out[3]);
            dst[1] = make_float4(out[4], out[5], out[6], out[7]);
        }
    }
}

// ---------------------------------------------------------------------------
// Prep 2: W -> g_Bhi/g_Blo cols [0,2048); Bexp -> cols [2048,2176).
// ---------------------------------------------------------------------------
__global__ __launch_bounds__(256) void split_wb_kernel(
    const float* __restrict__ W, const float* __restrict__ Bexp)
{
    const int o = blockIdx.x;
    const int tid = threadIdx.x;
    const float4* src = reinterpret_cast<const float4*>(W + (size_t)o * D_DIM);
    for (int i = tid; i < D_DIM / 4; i += 256) {
        float4 v = src[i];
        ushort4 hv, lv;
        hv.x = bf_hi(v.x); lv.x = bf_lo(v.x);
        hv.y = bf_hi(v.y); lv.y = bf_lo(v.y);
        hv.z = bf_hi(v.z); lv.z = bf_lo(v.z);
        hv.w = bf_hi(v.w); lv.w = bf_lo(v.w);
        *reinterpret_cast<ushort4*>(g_Bhi + (size_t)o * K_TOT + i * 4) = hv;
        *reinterpret_cast<ushort4*>(g_Blo + (size_t)o * K_TOT + i * 4) = lv;
    }
    if (tid < KLORA) {
        float v = Bexp[(size_t)tid * O_DIM + o];
        g_Bhi[(size_t)o * K_TOT + D_DIM + tid] = bf_hi(v);
        g_Blo[(size_t)o * K_TOT + D_DIM + tid] = bf_lo(v);
    }
}

// ---------------------------------------------------------------------------
// Prep 3: Acat^T splits: g_Achi[n][k], n = e*16+r.
// ---------------------------------------------------------------------------
__global__ __launch_bounds__(256) void split_acat_kernel(const float* __restrict__ A)
{
    const int n = blockIdx.x;
    const int e = n >> 4, r = n & 15;
    const int tid = threadIdx.x;
    for (int k = tid; k < D_DIM; k += 256) {
        float v = A[(size_t)e * D_DIM * R_DIM + (size_t)k * R_DIM + r];
        g_Achi[(size_t)n * D_DIM + k] = bf_hi(v);
        g_Aclo[(size_t)n * D_DIM + k] = bf_lo(v);
    }
}

// ---------------------------------------------------------------------------
// zgemm (fused 3-pass): Z = (X @ Acat) * rw -> bf16 splits, cols [2048,2176).
// Tile 64(M) x 128(N), BK=64, 3 stages. Stage = Ahi 8K | Alo 8K | Bh 16K | Bl 16K.
// 8 warps: wm = warp&1, wn = warp>>1; warp tile 32x32.  (unchanged from R9)
// ---------------------------------------------------------------------------
#define ZSTG 49152
#define ZSMEM (3 * ZSTG)

__global__ void __launch_bounds__(256, 1) zgemm_mma_kernel()
{
    extern __shared__ __align__(128) char smem[];
    const uint32_t sb = s2u(smem);
    const int tid = threadIdx.x;
    const int lane = tid & 31, warp = tid >> 5;
    const int wm = warp & 1, wn = warp >> 1;
    const int m0 = blockIdx.x * 64;

    float acc[2][4][4];
#pragma unroll
    for (int i = 0; i < 2; i++)
#pragma unroll
        for (int j = 0; j < 4; j++)
#pragma unroll
            for (int k = 0; k < 4; k++) acc[i][j][k] = 0.f;

    const int NT = 32;   // 2048 / 64
    const unsigned short* Ah = g_Ahi + (size_t)m0 * K_TOT;
    const unsigned short* Al = g_Alo + (size_t)m0 * K_TOT;

    auto load_chunk = [&](int t, int s) {
        const int k0 = t * 64;
        uint32_t Ab = sb + s * ZSTG;
#pragma unroll
        for (int j = 0; j < 2; j++) {               // A tiles: 64 rows * 8 chunks
            int idx = tid + j * 256;
            int row = idx >> 3, c = idx & 7;
            uint32_t off = tswz(row, c * 16);
            cp16(Ab + off,        Ah + (size_t)row * K_TOT + k0 + c * 8);
            cp16(Ab + 8192 + off, Al + (size_t)row * K_TOT + k0 + c * 8);
        }
#pragma unroll
        for (int j = 0; j < 4; j++) {               // B tiles: 128 rows * 8 chunks
            int idx = tid + j * 256;
            int row = idx >> 3, c = idx & 7;
            uint32_t off = tswz(row, c * 16);
            cp16(Ab + 16384 + off, g_Achi + (size_t)row * D_DIM + k0 + c * 8);
            cp16(Ab + 32768 + off, g_Aclo + (size_t)row * D_DIM + k0 + c * 8);
        }
    };

    load_chunk(0, 0); CP_COMMIT();
    load_chunk(1, 1); CP_COMMIT();

    for (int t = 0; t < NT; t++) {
        CP_WAIT1();
        __syncthreads();
        if (t + 2 < NT) load_chunk(t + 2, (t + 2) % 3);
        CP_COMMIT();
        const int s = t % 3;
        uint32_t Ab = sb + s * ZSTG;
#pragma unroll
        for (int kb = 0; kb < 4; kb++) {
            uint32_t ah[2][4], al[2][4], bh[2][4], bl[2][4];
            int colb = kb * 32 + (lane >> 4) * 16;
#pragma unroll
            for (int mt = 0; mt < 2; mt++) {
                uint32_t off = tswz(wm * 32 + mt * 16 + (lane & 15), colb);
                ldm_x4(ah[mt], Ab + off);
                ldm_x4(al[mt], Ab + 8192 + off);
            }
#pragma unroll
            for (int nt = 0; nt < 2; nt++) {
                uint32_t off = tswz(wn * 32 + nt * 16 + (lane & 15), colb);
                ldm_x4(bh[nt], Ab + 16384 + off);
                ldm_x4(bl[nt], Ab + 32768 + off);
            }
#pragma unroll
            for (int mt = 0; mt < 2; mt++)
#pragma unroll
                for (int ns = 0; ns < 4; ns++) {
                    uint32_t h0 = bh[ns >> 1][ns & 1], h1 = bh[ns >> 1][2 + (ns & 1)];
                    mma_bf16(acc[mt][ns], ah[mt], h0, h1);
                    mma_bf16(acc[mt][ns], al[mt], h0, h1);
                    mma_bf16(acc[mt][ns], ah[mt],
                             bl[ns >> 1][ns & 1], bl[ns >> 1][2 + (ns & 1)]);
                }
        }
        __syncthreads();
    }

    // epilogue: scale by router weight, split to bf16, store cols [2048,2176)
#pragma unroll
    for (int mt = 0; mt < 2; mt++)
#pragma unroll
        for (int ns = 0; ns < 4; ns++) {
            int m = m0 + wm * 32 + mt * 16 + (lane >> 2);
            int n = wn * 32 + ns * 8 + (lane & 3) * 2;
            int e = n >> 4;
            float w0 = g_rw[(size_t)m * E_NUM + e];
            float w1 = g_rw[(size_t)(m + 8) * E_NUM + e];
            float v0 = acc[mt][ns][0] * w0, v1 = acc[mt][ns][1] * w0;
            float v2 = acc[mt][ns][2] * w1, v3 = acc[mt][ns][3] * w1;
            ushort2 h0 = {bf_hi(v0), bf_hi(v1)}, l0 = {bf_lo(v0), bf_lo(v1)};
            ushort2 h1 = {bf_hi(v2), bf_hi(v3)}, l1 = {bf_lo(v2), bf_lo(v3)};
            *reinterpret_cast<ushort2*>(g_Ahi + (size_t)m * K_TOT + D_DIM + n) = h0;
            *reinterpret_cast<ushort2*>(g_Alo + (size_t)m * K_TOT + D_DIM + n) = l0;
            *reinterpret_cast<ushort2*>(g_Ahi + (size_t)(m + 8) * K_TOT + D_DIM + n) = h1;
            *reinterpret_cast<ushort2*>(g_Alo + (size_t)(m + 8) * K_TOT + D_DIM + n) = l1;
        }
}

// ---------------------------------------------------------------------------
// mgemm (fused 3-pass, R9 config): out = [X|Z] @ [W|Bcat]^T + bias.
// Tile 128(M) x 128(N), BK=64, 3 stages (64KB each = 192KB). grid 1024.
// 8 warps: wm = warp&3 (4), wn = warp>>2 (2); warp tile 32x64.
// ---------------------------------------------------------------------------
#define MSTG 65536
#define MSMEM (3 * MSTG)

__global__ void __launch_bounds__(256, 1) mgemm_mma_kernel(
    const float* __restrict__ bias, float* __restrict__ out)
{
    extern __shared__ __align__(128) char smem[];
    const uint32_t sb = s2u(smem);
    const int tid = threadIdx.x;
    const int lane = tid & 31, warp = tid >> 5;
    const int wm = warp & 3, wn = warp >> 2;
    const int n0 = blockIdx.x * 128;
    const int m0 = blockIdx.y * 128;

    float acc[2][8][4];
#pragma unroll
    for (int i = 0; i < 2; i++)
#pragma unroll
        for (int j = 0; j < 8; j++)
#pragma unroll
            for (int k = 0; k < 4; k++) acc[i][j][k] = 0.f;

    const int NT = 34;   // 2176 / 64
    const unsigned short* Ah = g_Ahi + (size_t)m0 * K_TOT;
    const unsigned short* Al = g_Alo + (size_t)m0 * K_TOT;
    const unsigned short* Bh = g_Bhi + (size_t)n0 * K_TOT;
    const unsigned short* Bl = g_Blo + (size_t)n0 * K_TOT;

    auto load_chunk = [&](int t, int s) {
        const int k0 = t * 64;
        uint32_t Ab = sb + s * MSTG;
#pragma unroll
        for (int j = 0; j < 4; j++) {               // 128 rows * 8 chunks per tile
            int idx = tid + j * 256;
            int row = idx >> 3, c = idx & 7;
            uint32_t off = tswz(row, c * 16);
            size_t go = (size_t)row * K_TOT + k0 + c * 8;
            cp16(Ab + off,         Ah + go);
            cp16(Ab + 16384 + off, Al + go);
            cp16(Ab + 32768 + off, Bh + go);
            cp16(Ab + 49152 + off, Bl + go);
        }
    };

    load_chunk(0, 0); CP_COMMIT();
    load_chunk(1, 1); CP_COMMIT();

    for (int t = 0; t < NT; t++) {
        CP_WAIT1();
        __syncthreads();
        if (t + 2 < NT) load_chunk(t + 2, (t + 2) % 3);
        CP_COMMIT();
        const int s = t % 3;
        uint32_t Ab = sb + s * MSTG;
#pragma unroll
        for (int kb = 0; kb < 4; kb++) {
            uint32_t ah[2][4], al[2][4], bh[4][4], bl[4][4];
            int colb = kb * 32 + (lane >> 4) * 16;
#pragma unroll
            for (int mt = 0; mt < 2; mt++) {
                uint32_t off = tswz(wm * 32 + mt * 16 + (lane & 15), colb);
                ldm_x4(ah[mt], Ab + off);
                ldm_x4(al[mt], Ab + 16384 + off);
            }
#pragma unroll
            for (int nt = 0; nt < 4; nt++) {
                uint32_t off = tswz(wn * 64 + nt * 16 + (lane & 15), colb);
                ldm_x4(bh[nt], Ab + 32768 + off);
                ldm_x4(bl[nt], Ab + 49152 + off);
            }
#pragma unroll
            for (int mt = 0; mt < 2; mt++)
#pragma unroll
                for (int ns = 0; ns < 8; ns++) {
                    uint32_t h0 = bh[ns >> 1][ns & 1], h1 = bh[ns >> 1][2 + (ns & 1)];
                    mma_bf16(acc[mt][ns], ah[mt], h0, h1);
                    mma_bf16(acc[mt][ns], al[mt], h0, h1);
                    mma_bf16(acc[mt][ns], ah[mt],
                             bl[ns >> 1][ns & 1], bl[ns >> 1][2 + (ns & 1)]);
                }
        }
        __syncthreads();
    }

    // epilogue: + bias, direct float2 stores
#pragma unroll
    for (int mt = 0; mt < 2; mt++)
#pragma unroll
        for (int ns = 0; ns < 8; ns++) {
            int m = m0 + wm * 32 + mt * 16 + (lane >> 2);
            int n = n0 + wn * 64 + ns * 8 + (lane & 3) * 2;
            float2 bv = *reinterpret_cast<const float2*>(bias + n);
            float2 v0 = {acc[mt][ns][0] + bv.x, acc[mt][ns][1] + bv.y};
            float2 v1 = {acc[mt][ns][2] + bv.x, acc[mt][ns][3] + bv.y};
            *reinterpret_cast<float2*>(out + (size_t)m * O_DIM + n) = v0;
            *reinterpret_cast<float2*>(out + (size_t)(m + 8) * O_DIM + n) = v1;
        }
}

// ---------------------------------------------------------------------------
extern "C" void kernel_launch(void* const* d_in, const int* in_sizes, int n_in,
                              void* d_out, int out_size)
{
    const float* x    = (const float*)d_in[0];
    const float* W    = (const float*)d_in[1];
    const float* bias = (const float*)d_in[2];
    const float* Wr   = (const float*)d_in[3];
    const float* A    = (const float*)d_in[4];
    const float* Bexp = (const float*)d_in[5];
    float* out = (float*)d_out;

    cudaFuncSetAttribute(prep_rs_kernel,
                         cudaFuncAttributeMaxDynamicSharedMemorySize, 65536);
    cudaFuncSetAttribute(zgemm_mma_kernel,
                         cudaFuncAttributeMaxDynamicSharedMemorySize, ZSMEM);
    cudaFuncSetAttribute(mgemm_mma_kernel,
                         cudaFuncAttributeMaxDynamicSharedMemorySize, MSMEM);

    prep_rs_kernel<<<M_TOT / 32, 256, 65536>>>(x, Wr);
    split_wb_kernel<<<O_DIM, 256>>>(W, Bexp);
    split_acat_kernel<<<KLORA, 256>>>(A);
    zgemm_mma_kernel<<<M_TOT / 64, 256, ZSMEM>>>();
    mgemm_mma_kernel<<<dim3(O_DIM / 128, M_TOT / 128), 256, MSMEM>>>(bias, out);
}

// round 14
// speedup vs baseline: 1.4313x; 1.3323x over previous
#include <cuda_runtime.h>
#include <cuda_fp16.h>
#include <cstdint>

#define M_TOT 8192
#define D_DIM 2048
#define O_DIM 2048
#define E_NUM 8
#define R_DIM 16
#define KLORA 128
#define K_TOT 2176          // D_DIM + KLORA

// ---------------- scratch (fp16 stored as ushort) ----------------
__device__ float g_rw[M_TOT * E_NUM];
__device__ unsigned short g_Ah[(size_t)M_TOT * K_TOT];   // [X|Z] fp16 hi
__device__ unsigned short g_Al[(size_t)M_TOT * K_TOT];   // [X|Z] fp16 lo (residual)
__device__ unsigned short g_Bh[(size_t)O_DIM * K_TOT];   // [W|Bcat] fp16 (single)
__device__ unsigned short g_Ach[(size_t)KLORA * D_DIM];  // Acat^T fp16 (single)

// ---------------- helpers ----------------
__device__ __forceinline__ uint32_t s2u(const void* p) {
    uint32_t a;
    asm("{ .reg .u64 t; cvta.to.shared.u64 t, %1; cvt.u32.u64 %0, t; }"
        : "=r"(a) : "l"(p));
    return a;
}
__device__ __forceinline__ void cp16(uint32_t dst, const void* src) {
    asm volatile("cp.async.cg.shared.global [%0], [%1], 16;" :: "r"(dst), "l"(src));
}
#define CP_COMMIT() asm volatile("cp.async.commit_group;" ::: "memory")
#define CP_WAIT1()  asm volatile("cp.async.wait_group 1;" ::: "memory")

__device__ __forceinline__ void ldm_x4(uint32_t* r, uint32_t addr) {
    asm volatile("ldmatrix.sync.aligned.m8n8.x4.shared.b16 {%0,%1,%2,%3}, [%4];"
        : "=r"(r[0]), "=r"(r[1]), "=r"(r[2]), "=r"(r[3]) : "r"(addr));
}
__device__ __forceinline__ void mma_fp16(float* d, const uint32_t* a,
                                         uint32_t b0, uint32_t b1) {
    asm volatile(
        "mma.sync.aligned.m16n8k16.row.col.f32.f16.f16.f32 "
        "{%0,%1,%2,%3}, {%4,%5,%6,%7}, {%8,%9}, {%0,%1,%2,%3};"
        : "+f"(d[0]), "+f"(d[1]), "+f"(d[2]), "+f"(d[3])
        : "r"(a[0]), "r"(a[1]), "r"(a[2]), "r"(a[3]), "r"(b0), "r"(b1));
}
__device__ __forceinline__ unsigned short hp(float v) {
    return __half_as_ushort(__float2half_rn(v));
}
__device__ __forceinline__ unsigned short hp_lo(float v) {
    float h = __half2float(__float2half_rn(v));
    return __half_as_ushort(__float2half_rn(v - h));
}

// swizzled byte offset within a tile: row, 16B-chunk byte offset (0..127)
__device__ __forceinline__ uint32_t tswz(int row, int cbyte) {
    return (uint32_t)(row * 128 + (cbyte ^ ((row & 7) << 4)));
}

// ---------------------------------------------------------------------------
// Prep 1 (warp-parallel): x -> fp16 hi/lo splits into cols [0,2048);
// router top-2 softmax -> g_rw. 32 rows per block, 4 rows per warp.
// ---------------------------------------------------------------------------
__global__ __launch_bounds__(256) void prep_rs_kernel(
    const float* __restrict__ x, const float* __restrict__ Wr)
{
    extern __shared__ float wr_s[];   // 16384 floats = 64KB
    const int tid = threadIdx.x;
    const int lane = tid & 31, warp = tid >> 5;

    for (int i = tid; i < 4096; i += 256)
        reinterpret_cast<float4*>(wr_s)[i] = reinterpret_cast<const float4*>(Wr)[i];
    __syncthreads();
    const float4* wr4 = reinterpret_cast<const float4*>(wr_s);

    const int m0 = blockIdx.x * 32;
#pragma unroll
    for (int r = 0; r < 4; r++) {
        const int m = m0 + warp * 4 + r;
        const float4* xr = reinterpret_cast<const float4*>(x + (size_t)m * D_DIM);
        float acc[E_NUM];
#pragma unroll
        for (int e = 0; e < E_NUM; e++) acc[e] = 0.f;

#pragma unroll 4
        for (int i = lane; i < D_DIM / 4; i += 32) {
            float4 xv = xr[i];
            ushort4 hv, lv;
            hv.x = hp(xv.x); lv.x = hp_lo(xv.x);
            hv.y = hp(xv.y); lv.y = hp_lo(xv.y);
            hv.z = hp(xv.z); lv.z = hp_lo(xv.z);
            hv.w = hp(xv.w); lv.w = hp_lo(xv.w);
            *reinterpret_cast<ushort4*>(g_Ah + (size_t)m * K_TOT + i * 4) = hv;
            *reinterpret_cast<ushort4*>(g_Al + (size_t)m * K_TOT + i * 4) = lv;
#pragma unroll
            for (int e = 0; e < E_NUM; e++) {
                float4 wv = wr4[e * 512 + i];
                acc[e] += xv.x * wv.x + xv.y * wv.y + xv.z * wv.z + xv.w * wv.w;
            }
        }
#pragma unroll
        for (int e = 0; e < E_NUM; e++) {
#pragma unroll
            for (int off = 16; off > 0; off >>= 1)
                acc[e] += __shfl_xor_sync(0xffffffffu, acc[e], off);
        }
        if (lane == 0) {
            int i1 = 0;
#pragma unroll
            for (int e = 1; e < E_NUM; e++) if (acc[e] > acc[i1]) i1 = e;
            int i2 = -1;
#pragma unroll
            for (int e = 0; e < E_NUM; e++) {
                if (e == i1) continue;
                if (i2 < 0 || acc[e] > acc[i2]) i2 = e;
            }
            float e2 = __expf(acc[i2] - acc[i1]);
            float inv = 1.0f / (1.0f + e2);
            float out[E_NUM];
#pragma unroll
            for (int e = 0; e < E_NUM; e++) out[e] = 0.f;
            out[i1] = inv;
            out[i2] = e2 * inv;
            float4* dst = reinterpret_cast<float4*>(g_rw + (size_t)m * E_NUM);
            dst[0] = make_float4(out[0], out[1], out[2], out[3]);
            dst[1] = make_float4(out[4], out[5], out[6], out[7]);
        }
    }
}

// ---------------------------------------------------------------------------
// Prep 2: W -> g_Bh cols [0,2048); Bexp -> cols [2048,2176). Single fp16.
// ---------------------------------------------------------------------------
__global__ __launch_bounds__(256) void split_wb_kernel(
    const float* __restrict__ W, const float* __restrict__ Bexp)
{
    const int o = blockIdx.x;
    const int tid = threadIdx.x;
    const float4* src = reinterpret_cast<const float4*>(W + (size_t)o * D_DIM);
    for (int i = tid; i < D_DIM / 4; i += 256) {
        float4 v = src[i];
        ushort4 hv;
        hv.x = hp(v.x); hv.y = hp(v.y); hv.z = hp(v.z); hv.w = hp(v.w);
        *reinterpret_cast<ushort4*>(g_Bh + (size_t)o * K_TOT + i * 4) = hv;
    }
    if (tid < KLORA)
        g_Bh[(size_t)o * K_TOT + D_DIM + tid] = hp(Bexp[(size_t)tid * O_DIM + o]);
}

// ---------------------------------------------------------------------------
// Prep 3: Acat^T fp16: g_Ach[n][k], n = e*16+r.
// ---------------------------------------------------------------------------
__global__ __launch_bounds__(256) void split_acat_kernel(const float* __restrict__ A)
{
    const int n = blockIdx.x;
    const int e = n >> 4, r = n & 15;
    const int tid = threadIdx.x;
    for (int k = tid; k < D_DIM; k += 256)
        g_Ach[(size_t)n * D_DIM + k] =
            hp(A[(size_t)e * D_DIM * R_DIM + (size_t)k * R_DIM + r]);
}

// ---------------------------------------------------------------------------
// zgemm (fp16 2-pass): Z = (X @ Acat) * rw -> fp16 splits, cols [2048,2176).
// Tile 64(M) x 128(N), BK=64, 3 stages. Stage = Ah 8K | Al 8K | Bh 16K = 32KB.
// 8 warps: wm = warp&1, wn = warp>>1; warp tile 32x32.
// ---------------------------------------------------------------------------
#define ZSTG 32768
#define ZSMEM (3 * ZSTG)

__global__ void __launch_bounds__(256, 1) zgemm_mma_kernel()
{
    extern __shared__ __align__(128) char smem[];
    const uint32_t sb = s2u(smem);
    const int tid = threadIdx.x;
    const int lane = tid & 31, warp = tid >> 5;
    const int wm = warp & 1, wn = warp >> 1;
    const int m0 = blockIdx.x * 64;

    float acc[2][4][4];
#pragma unroll
    for (int i = 0; i < 2; i++)
#pragma unroll
        for (int j = 0; j < 4; j++)
#pragma unroll
            for (int k = 0; k < 4; k++) acc[i][j][k] = 0.f;

    const int NT = 32;   // 2048 / 64
    const unsigned short* Ah = g_Ah + (size_t)m0 * K_TOT;
    const unsigned short* Al = g_Al + (size_t)m0 * K_TOT;

    auto load_chunk = [&](int t, int s) {
        const int k0 = t * 64;
        uint32_t Ab = sb + s * ZSTG;
#pragma unroll
        for (int j = 0; j < 2; j++) {               // A tiles: 64 rows * 8 chunks
            int idx = tid + j * 256;
            int row = idx >> 3, c = idx & 7;
            uint32_t off = tswz(row, c * 16);
            cp16(Ab + off,        Ah + (size_t)row * K_TOT + k0 + c * 8);
            cp16(Ab + 8192 + off, Al + (size_t)row * K_TOT + k0 + c * 8);
        }
#pragma unroll
        for (int j = 0; j < 4; j++) {               // B tile: 128 rows * 8 chunks
            int idx = tid + j * 256;
            int row = idx >> 3, c = idx & 7;
            cp16(Ab + 16384 + tswz(row, c * 16),
                 g_Ach + (size_t)row * D_DIM + k0 + c * 8);
        }
    };

    load_chunk(0, 0); CP_COMMIT();
    load_chunk(1, 1); CP_COMMIT();

    for (int t = 0; t < NT; t++) {
        CP_WAIT1();
        __syncthreads();
        if (t + 2 < NT) load_chunk(t + 2, (t + 2) % 3);
        CP_COMMIT();
        const int s = t % 3;
        uint32_t Ab = sb + s * ZSTG;
#pragma unroll
        for (int kb = 0; kb < 4; kb++) {
            uint32_t ah[2][4], al[2][4], bh[2][4];
            int colb = kb * 32 + (lane >> 4) * 16;
#pragma unroll
            for (int mt = 0; mt < 2; mt++) {
                uint32_t off = tswz(wm * 32 + mt * 16 + (lane & 15), colb);
                ldm_x4(ah[mt], Ab + off);
                ldm_x4(al[mt], Ab + 8192 + off);
            }
#pragma unroll
            for (int nt = 0; nt < 2; nt++) {
                uint32_t off = tswz(wn * 32 + nt * 16 + (lane & 15), colb);
                ldm_x4(bh[nt], Ab + 16384 + off);
            }
#pragma unroll
            for (int mt = 0; mt < 2; mt++)
#pragma unroll
                for (int ns = 0; ns < 4; ns++) {
                    uint32_t h0 = bh[ns >> 1][ns & 1], h1 = bh[ns >> 1][2 + (ns & 1)];
                    mma_fp16(acc[mt][ns], ah[mt], h0, h1);
                    mma_fp16(acc[mt][ns], al[mt], h0, h1);
                }
        }
        __syncthreads();
    }

    // epilogue: scale by router weight, split to fp16, store cols [2048,2176)
#pragma unroll
    for (int mt = 0; mt < 2; mt++)
#pragma unroll
        for (int ns = 0; ns < 4; ns++) {
            int m = m0 + wm * 32 + mt * 16 + (lane >> 2);
            int n = wn * 32 + ns * 8 + (lane & 3) * 2;
            int e = n >> 4;
            float w0 = g_rw[(size_t)m * E_NUM + e];
            float w1 = g_rw[(size_t)(m + 8) * E_NUM + e];
            float v0 = acc[mt][ns][0] * w0, v1 = acc[mt][ns][1] * w0;
            float v2 = acc[mt][ns][2] * w1, v3 = acc[mt][ns][3] * w1;
            ushort2 h0 = {hp(v0), hp(v1)}, l0 = {hp_lo(v0), hp_lo(v1)};
            ushort2 h1 = {hp(v2), hp(v3)}, l1 = {hp_lo(v2), hp_lo(v3)};
            *reinterpret_cast<ushort2*>(g_Ah + (size_t)m * K_TOT + D_DIM + n) = h0;
            *reinterpret_cast<ushort2*>(g_Al + (size_t)m * K_TOT + D_DIM + n) = l0;
            *reinterpret_cast<ushort2*>(g_Ah + (size_t)(m + 8) * K_TOT + D_DIM + n) = h1;
            *reinterpret_cast<ushort2*>(g_Al + (size_t)(m + 8) * K_TOT + D_DIM + n) = l1;
        }
}

// ---------------------------------------------------------------------------
// mgemm (fp16 2-pass): out = [X|Z] @ [W|Bcat]^T + bias.
// Tile 128(M) x 128(N), BK=64, 3 stages. Stage = Ah 16K | Al 16K | Bh 16K = 48KB.
// grid 1024. 8 warps: wm = warp&3 (4), wn = warp>>2 (2); warp tile 32x64.
// ---------------------------------------------------------------------------
#define MSTG 49152
#define MSMEM (3 * MSTG)

__global__ void __launch_bounds__(256, 1) mgemm_mma_kernel(
    const float* __restrict__ bias, float* __restrict__ out)
{
    extern __shared__ __align__(128) char smem[];
    const uint32_t sb = s2u(smem);
    const int tid = threadIdx.x;
    const int lane = tid & 31, warp = tid >> 5;
    const int wm = warp & 3, wn = warp >> 2;
    const int n0 = blockIdx.x * 128;
    const int m0 = blockIdx.y * 128;

    float acc[2][8][4];
#pragma unroll
    for (int i = 0; i < 2; i++)
#pragma unroll
        for (int j = 0; j < 8; j++)
#pragma unroll
            for (int k = 0; k < 4; k++) acc[i][j][k] = 0.f;

    const int NT = 34;   // 2176 / 64
    const unsigned short* Ah = g_Ah + (size_t)m0 * K_TOT;
    const unsigned short* Al = g_Al + (size_t)m0 * K_TOT;
    const unsigned short* Bh = g_Bh + (size_t)n0 * K_TOT;

    auto load_chunk = [&](int t, int s) {
        const int k0 = t * 64;
        uint32_t Ab = sb + s * MSTG;
#pragma unroll
        for (int j = 0; j < 4; j++) {               // 128 rows * 8 chunks per tile
            int idx = tid + j * 256;
            int row = idx >> 3, c = idx & 7;
            uint32_t off = tswz(row, c * 16);
            size_t go = (size_t)row * K_TOT + k0 + c * 8;
            cp16(Ab + off,         Ah + go);
            cp16(Ab + 16384 + off, Al + go);
            cp16(Ab + 32768 + off, Bh + go);
        }
    };

    load_chunk(0, 0); CP_COMMIT();
    load_chunk(1, 1); CP_COMMIT();

    for (int t = 0; t < NT; t++) {
        CP_WAIT1();
        __syncthreads();
        if (t + 2 < NT) load_chunk(t + 2, (t + 2) % 3);
        CP_COMMIT();
        const int s = t % 3;
        uint32_t Ab = sb + s * MSTG;
#pragma unroll
        for (int kb = 0; kb < 4; kb++) {
            uint32_t ah[2][4], al[2][4], bh[4][4];
            int colb = kb * 32 + (lane >> 4) * 16;
#pragma unroll
            for (int mt = 0; mt < 2; mt++) {
                uint32_t off = tswz(wm * 32 + mt * 16 + (lane & 15), colb);
                ldm_x4(ah[mt], Ab + off);
                ldm_x4(al[mt], Ab + 16384 + off);
            }
#pragma unroll
            for (int nt = 0; nt < 4; nt++) {
                uint32_t off = tswz(wn * 64 + nt * 16 + (lane & 15), colb);
                ldm_x4(bh[nt], Ab + 32768 + off);
            }
#pragma unroll
            for (int mt = 0; mt < 2; mt++)
#pragma unroll
                for (int ns = 0; ns < 8; ns++) {
                    uint32_t h0 = bh[ns >> 1][ns & 1], h1 = bh[ns >> 1][2 + (ns & 1)];
                    mma_fp16(acc[mt][ns], ah[mt], h0, h1);
                    mma_fp16(acc[mt][ns], al[mt], h0, h1);
                }
        }
        __syncthreads();
    }

    // epilogue: + bias, direct float2 stores
#pragma unroll
    for (int mt = 0; mt < 2; mt++)
#pragma unroll
        for (int ns = 0; ns < 8; ns++) {
            int m = m0 + wm * 32 + mt * 16 + (lane >> 2);
            int n = n0 + wn * 64 + ns * 8 + (lane & 3) * 2;
            float2 bv = *reinterpret_cast<const float2*>(bias + n);
            float2 v0 = {acc[mt][ns][0] + bv.x, acc[mt][ns][1] + bv.y};
            float2 v1 = {acc[mt][ns][2] + bv.x, acc[mt][ns][3] + bv.y};
            *reinterpret_cast<float2*>(out + (size_t)m * O_DIM + n) = v0;
            *reinterpret_cast<float2*>(out + (size_t)(m + 8) * O_DIM + n) = v1;
        }
}

// ---------------------------------------------------------------------------
extern "C" void kernel_launch(void* const* d_in, const int* in_sizes, int n_in,
                              void* d_out, int out_size)
{
    const float* x    = (const float*)d_in[0];
    const float* W    = (const float*)d_in[1];
    const float* bias = (const float*)d_in[2];
    const float* Wr   = (const float*)d_in[3];
    const float* A    = (const float*)d_in[4];
    const float* Bexp = (const float*)d_in[5];
    float* out = (float*)d_out;

    cudaFuncSetAttribute(prep_rs_kernel,
                         cudaFuncAttributeMaxDynamicSharedMemorySize, 65536);
    cudaFuncSetAttribute(zgemm_mma_kernel,
                         cudaFuncAttributeMaxDynamicSharedMemorySize, ZSMEM);
    cudaFuncSetAttribute(mgemm_mma_kernel,
                         cudaFuncAttributeMaxDynamicSharedMemorySize, MSMEM);

    prep_rs_kernel<<<M_TOT / 32, 256, 65536>>>(x, Wr);
    split_wb_kernel<<<O_DIM, 256>>>(W, Bexp);
    split_acat_kernel<<<KLORA, 256>>>(A);
    zgemm_mma_kernel<<<M_TOT / 64, 256, ZSMEM>>>();
    mgemm_mma_kernel<<<dim3(O_DIM / 128, M_TOT / 128), 256, MSMEM>>>(bias, out);
}

// round 15
// speedup vs baseline: 2.5982x; 1.8153x over previous
#include <cuda_runtime.h>
#include <cuda_fp16.h>
#include <cstdint>

#define M_TOT 8192
#define D_DIM 2048
#define O_DIM 2048
#define E_NUM 8
#define R_DIM 16
#define KLORA 128
#define K_TOT 2176          // D_DIM + KLORA

// ---------------- scratch (fp16 stored as ushort) ----------------
__device__ float g_rw[M_TOT * E_NUM];
__device__ unsigned short g_Ah[(size_t)M_TOT * K_TOT];   // [X|Z] fp16
__device__ unsigned short g_Bh[(size_t)O_DIM * K_TOT];   // [W|Bcat] fp16
__device__ unsigned short g_Ach[(size_t)KLORA * D_DIM];  // Acat^T fp16

// ---------------- helpers ----------------
__device__ __forceinline__ uint32_t s2u(const void* p) {
    uint32_t a;
    asm("{ .reg .u64 t; cvta.to.shared.u64 t, %1; cvt.u32.u64 %0, t; }"
        : "=r"(a) : "l"(p));
    return a;
}
__device__ __forceinline__ void cp16(uint32_t dst, const void* src) {
    asm volatile("cp.async.cg.shared.global [%0], [%1], 16;" :: "r"(dst), "l"(src));
}
#define CP_COMMIT() asm volatile("cp.async.commit_group;" ::: "memory")
#define CP_WAIT1()  asm volatile("cp.async.wait_group 1;" ::: "memory")

__device__ __forceinline__ void ldm_x4(uint32_t* r, uint32_t addr) {
    asm volatile("ldmatrix.sync.aligned.m8n8.x4.shared.b16 {%0,%1,%2,%3}, [%4];"
        : "=r"(r[0]), "=r"(r[1]), "=r"(r[2]), "=r"(r[3]) : "r"(addr));
}
__device__ __forceinline__ void mma_fp16(float* d, const uint32_t* a,
                                         uint32_t b0, uint32_t b1) {
    asm volatile(
        "mma.sync.aligned.m16n8k16.row.col.f32.f16.f16.f32 "
        "{%0,%1,%2,%3}, {%4,%5,%6,%7}, {%8,%9}, {%0,%1,%2,%3};"
        : "+f"(d[0]), "+f"(d[1]), "+f"(d[2]), "+f"(d[3])
        : "r"(a[0]), "r"(a[1]), "r"(a[2]), "r"(a[3]), "r"(b0), "r"(b1));
}
__device__ __forceinline__ unsigned short hp(float v) {
    return __half_as_ushort(__float2half_rn(v));
}

// swizzled byte offset within a tile: row, 16B-chunk byte offset (0..127)
__device__ __forceinline__ uint32_t tswz(int row, int cbyte) {
    return (uint32_t)(row * 128 + (cbyte ^ ((row & 7) << 4)));
}

// ---------------------------------------------------------------------------
// Prep 1 (warp-parallel): x -> fp16 into cols [0,2048);
// router top-2 softmax -> g_rw. 32 rows per block, 4 rows per warp.
// ---------------------------------------------------------------------------
__global__ __launch_bounds__(256) void prep_rs_kernel(
    const float* __restrict__ x, const float* __restrict__ Wr)
{
    extern __shared__ float wr_s[];   // 16384 floats = 64KB
    const int tid = threadIdx.x;
    const int lane = tid & 31, warp = tid >> 5;

    for (int i = tid; i < 4096; i += 256)
        reinterpret_cast<float4*>(wr_s)[i] = reinterpret_cast<const float4*>(Wr)[i];
    __syncthreads();
    const float4* wr4 = reinterpret_cast<const float4*>(wr_s);

    const int m0 = blockIdx.x * 32;
#pragma unroll
    for (int r = 0; r < 4; r++) {
        const int m = m0 + warp * 4 + r;
        const float4* xr = reinterpret_cast<const float4*>(x + (size_t)m * D_DIM);
        float acc[E_NUM];
#pragma unroll
        for (int e = 0; e < E_NUM; e++) acc[e] = 0.f;

#pragma unroll 4
        for (int i = lane; i < D_DIM / 4; i += 32) {
            float4 xv = xr[i];
            ushort4 hv;
            hv.x = hp(xv.x); hv.y = hp(xv.y);
            hv.z = hp(xv.z); hv.w = hp(xv.w);
            *reinterpret_cast<ushort4*>(g_Ah + (size_t)m * K_TOT + i * 4) = hv;
#pragma unroll
            for (int e = 0; e < E_NUM; e++) {
                float4 wv = wr4[e * 512 + i];
                acc[e] += xv.x * wv.x + xv.y * wv.y + xv.z * wv.z + xv.w * wv.w;
            }
        }
#pragma unroll
        for (int e = 0; e < E_NUM; e++) {
#pragma unroll
            for (int off = 16; off > 0; off >>= 1)
                acc[e] += __shfl_xor_sync(0xffffffffu, acc[e], off);
        }
        if (lane == 0) {
            int i1 = 0;
#pragma unroll
            for (int e = 1; e < E_NUM; e++) if (acc[e] > acc[i1]) i1 = e;
            int i2 = -1;
#pragma unroll
            for (int e = 0; e < E_NUM; e++) {
                if (e == i1) continue;
                if (i2 < 0 || acc[e] > acc[i2]) i2 = e;
            }
            float e2 = __expf(acc[i2] - acc[i1]);
            float inv = 1.0f / (1.0f + e2);
            float out[E_NUM];
#pragma unroll
            for (int e = 0; e < E_NUM; e++) out[e] = 0.f;
            out[i1] = inv;
            out[i2] = e2 * inv;
            float4* dst = reinterpret_cast<float4*>(g_rw + (size_t)m * E_NUM);
            dst[0] = make_float4(out[0], out[1], out[2], out[3]);
            dst[1] = make_float4(out[4], out[5], out[6], out[7]);
        }
    }
}

// ---------------------------------------------------------------------------
// Prep 2: W -> g_Bh cols [0,2048); Bexp -> cols [2048,2176).
// ---------------------------------------------------------------------------
__global__ __launch_bounds__(256) void split_wb_kernel(
    const float* __restrict__ W, const float* __restrict__ Bexp)
{
    const int o = blockIdx.x;
    const int tid = threadIdx.x;
    const float4* src = reinterpret_cast<const float4*>(W + (size_t)o * D_DIM);
    for (int i = tid; i < D_DIM / 4; i += 256) {
        float4 v = src[i];
        ushort4 hv;
        hv.x = hp(v.x); hv.y = hp(v.y); hv.z = hp(v.z); hv.w = hp(v.w);
        *reinterpret_cast<ushort4*>(g_Bh + (size_t)o * K_TOT + i * 4) = hv;
    }
    if (tid < KLORA)
        g_Bh[(size_t)o * K_TOT + D_DIM + tid] = hp(Bexp[(size_t)tid * O_DIM + o]);
}

// ---------------------------------------------------------------------------
// Prep 3: Acat^T fp16: g_Ach[n][k], n = e*16+r.
// ---------------------------------------------------------------------------
__global__ __launch_bounds__(256) void split_acat_kernel(const float* __restrict__ A)
{
    const int n = blockIdx.x;
    const int e = n >> 4, r = n & 15;
    const int tid = threadIdx.x;
    for (int k = tid; k < D_DIM; k += 256)
        g_Ach[(size_t)n * D_DIM + k] =
            hp(A[(size_t)e * D_DIM * R_DIM + (size_t)k * R_DIM + r]);
}

// ---------------------------------------------------------------------------
// zgemm (fp16 single-pass): Z = (X @ Acat) * rw -> fp16, cols [2048,2176).
// Tile 64(M) x 128(N), BK=64, 3 stages. Stage = A 8K | B 16K = 24KB.
// 8 warps: wm = warp&1, wn = warp>>1; warp tile 32x32.
// ---------------------------------------------------------------------------
#define ZSTG 24576
#define ZSMEM (3 * ZSTG)

__global__ void __launch_bounds__(256, 1) zgemm_mma_kernel()
{
    extern __shared__ __align__(128) char smem[];
    const uint32_t sb = s2u(smem);
    const int tid = threadIdx.x;
    const int lane = tid & 31, warp = tid >> 5;
    const int wm = warp & 1, wn = warp >> 1;
    const int m0 = blockIdx.x * 64;

    float acc[2][4][4];
#pragma unroll
    for (int i = 0; i < 2; i++)
#pragma unroll
        for (int j = 0; j < 4; j++)
#pragma unroll
            for (int k = 0; k < 4; k++) acc[i][j][k] = 0.f;

    const int NT = 32;   // 2048 / 64
    const unsigned short* Ah = g_Ah + (size_t)m0 * K_TOT;

    auto load_chunk = [&](int t, int s) {
        const int k0 = t * 64;
        uint32_t Ab = sb + s * ZSTG;
#pragma unroll
        for (int j = 0; j < 2; j++) {               // A tile: 64 rows * 8 chunks
            int idx = tid + j * 256;
            int row = idx >> 3, c = idx & 7;
            cp16(Ab + tswz(row, c * 16), Ah + (size_t)row * K_TOT + k0 + c * 8);
        }
#pragma unroll
        for (int j = 0; j < 4; j++) {               // B tile: 128 rows * 8 chunks
            int idx = tid + j * 256;
            int row = idx >> 3, c = idx & 7;
            cp16(Ab + 8192 + tswz(row, c * 16),
                 g_Ach + (size_t)row * D_DIM + k0 + c * 8);
        }
    };

    load_chunk(0, 0); CP_COMMIT();
    load_chunk(1, 1); CP_COMMIT();

    for (int t = 0; t < NT; t++) {
        CP_WAIT1();
        __syncthreads();
        if (t + 2 < NT) load_chunk(t + 2, (t + 2) % 3);
        CP_COMMIT();
        const int s = t % 3;
        uint32_t Ab = sb + s * ZSTG;
#pragma unroll
        for (int kb = 0; kb < 4; kb++) {
            uint32_t ah[2][4], bh[2][4];
            int colb = kb * 32 + (lane >> 4) * 16;
#pragma unroll
            for (int mt = 0; mt < 2; mt++)
                ldm_x4(ah[mt], Ab + tswz(wm * 32 + mt * 16 + (lane & 15), colb));
#pragma unroll
            for (int nt = 0; nt < 2; nt++)
                ldm_x4(bh[nt], Ab + 8192 + tswz(wn * 32 + nt * 16 + (lane & 15), colb));
#pragma unroll
            for (int mt = 0; mt < 2; mt++)
#pragma unroll
                for (int ns = 0; ns < 4; ns++)
                    mma_fp16(acc[mt][ns], ah[mt],
                             bh[ns >> 1][ns & 1], bh[ns >> 1][2 + (ns & 1)]);
        }
        __syncthreads();
    }

    // epilogue: scale by router weight, store fp16 into cols [2048,2176)
#pragma unroll
    for (int mt = 0; mt < 2; mt++)
#pragma unroll
        for (int ns = 0; ns < 4; ns++) {
            int m = m0 + wm * 32 + mt * 16 + (lane >> 2);
            int n = wn * 32 + ns * 8 + (lane & 3) * 2;
            int e = n >> 4;
            float w0 = g_rw[(size_t)m * E_NUM + e];
            float w1 = g_rw[(size_t)(m + 8) * E_NUM + e];
            ushort2 h0 = {hp(acc[mt][ns][0] * w0), hp(acc[mt][ns][1] * w0)};
            ushort2 h1 = {hp(acc[mt][ns][2] * w1), hp(acc[mt][ns][3] * w1)};
            *reinterpret_cast<ushort2*>(g_Ah + (size_t)m * K_TOT + D_DIM + n) = h0;
            *reinterpret_cast<ushort2*>(g_Ah + (size_t)(m + 8) * K_TOT + D_DIM + n) = h1;
        }
}

// ---------------------------------------------------------------------------
// mgemm (fp16 single-pass): out = [X|Z] @ [W|Bcat]^T + bias.
// Tile 128(M) x 128(N), BK=64, 3 stages. Stage = A 16K | B 16K = 32KB.
// grid 1024. 8 warps: wm = warp&3 (4), wn = warp>>2 (2); warp tile 32x64.
// ---------------------------------------------------------------------------
#define MSTG 32768
#define MSMEM (3 * MSTG)

__global__ void __launch_bounds__(256, 1) mgemm_mma_kernel(
    const float* __restrict__ bias, float* __restrict__ out)
{
    extern __shared__ __align__(128) char smem[];
    const uint32_t sb = s2u(smem);
    const int tid = threadIdx.x;
    const int lane = tid & 31, warp = tid >> 5;
    const int wm = warp & 3, wn = warp >> 2;
    const int n0 = blockIdx.x * 128;
    const int m0 = blockIdx.y * 128;

    float acc[2][8][4];
#pragma unroll
    for (int i = 0; i < 2; i++)
#pragma unroll
        for (int j = 0; j < 8; j++)
#pragma unroll
            for (int k = 0; k < 4; k++) acc[i][j][k] = 0.f;

    const int NT = 34;   // 2176 / 64
    const unsigned short* Ah = g_Ah + (size_t)m0 * K_TOT;
    const unsigned short* Bh = g_Bh + (size_t)n0 * K_TOT;

    auto load_chunk = [&](int t, int s) {
        const int k0 = t * 64;
        uint32_t Ab = sb + s * MSTG;
#pragma unroll
        for (int j = 0; j < 4; j++) {               // 128 rows * 8 chunks per tile
            int idx = tid + j * 256;
            int row = idx >> 3, c = idx & 7;
            uint32_t off = tswz(row, c * 16);
            size_t go = (size_t)row * K_TOT + k0 + c * 8;
            cp16(Ab + off,         Ah + go);
            cp16(Ab + 16384 + off, Bh + go);
        }
    };

    load_chunk(0, 0); CP_COMMIT();
    load_chunk(1, 1); CP_COMMIT();

    for (int t = 0; t < NT; t++) {
        CP_WAIT1();
        __syncthreads();
        if (t + 2 < NT) load_chunk(t + 2, (t + 2) % 3);
        CP_COMMIT();
        const int s = t % 3;
        uint32_t Ab = sb + s * MSTG;
#pragma unroll
        for (int kb = 0; kb < 4; kb++) {
            uint32_t ah[2][4], bh[4][4];
            int colb = kb * 32 + (lane >> 4) * 16;
#pragma unroll
            for (int mt = 0; mt < 2; mt++)
                ldm_x4(ah[mt], Ab + tswz(wm * 32 + mt * 16 + (lane & 15), colb));
#pragma unroll
            for (int nt = 0; nt < 4; nt++)
                ldm_x4(bh[nt], Ab + 16384 + tswz(wn * 64 + nt * 16 + (lane & 15), colb));
#pragma unroll
            for (int mt = 0; mt < 2; mt++)
#pragma unroll
                for (int ns = 0; ns < 8; ns++)
                    mma_fp16(acc[mt][ns], ah[mt],
                             bh[ns >> 1][ns & 1], bh[ns >> 1][2 + (ns & 1)]);
        }
        __syncthreads();
    }

    // epilogue: + bias, direct float2 stores
#pragma unroll
    for (int mt = 0; mt < 2; mt++)
#pragma unroll
        for (int ns = 0; ns < 8; ns++) {
            int m = m0 + wm * 32 + mt * 16 + (lane >> 2);
            int n = n0 + wn * 64 + ns * 8 + (lane & 3) * 2;
            float2 bv = *reinterpret_cast<const float2*>(bias + n);
            float2 v0 = {acc[mt][ns][0] + bv.x, acc[mt][ns][1] + bv.y};
            float2 v1 = {acc[mt][ns][2] + bv.x, acc[mt][ns][3] + bv.y};
            *reinterpret_cast<float2*>(out + (size_t)m * O_DIM + n) = v0;
            *reinterpret_cast<float2*>(out + (size_t)(m + 8) * O_DIM + n) = v1;
        }
}

// ---------------------------------------------------------------------------
extern "C" void kernel_launch(void* const* d_in, const int* in_sizes, int n_in,
                              void* d_out, int out_size)
{
    const float* x    = (const float*)d_in[0];
    const float* W    = (const float*)d_in[1];
    const float* bias = (const float*)d_in[2];
    const float* Wr   = (const float*)d_in[3];
    const float* A    = (const float*)d_in[4];
    const float* Bexp = (const float*)d_in[5];
    float* out = (float*)d_out;

    cudaFuncSetAttribute(prep_rs_kernel,
                         cudaFuncAttributeMaxDynamicSharedMemorySize, 65536);
    cudaFuncSetAttribute(zgemm_mma_kernel,
                         cudaFuncAttributeMaxDynamicSharedMemorySize, ZSMEM);
    cudaFuncSetAttribute(mgemm_mma_kernel,
                         cudaFuncAttributeMaxDynamicSharedMemorySize, MSMEM);

    prep_rs_kernel<<<M_TOT / 32, 256, 65536>>>(x, Wr);
    split_wb_kernel<<<O_DIM, 256>>>(W, Bexp);
    split_acat_kernel<<<KLORA, 256>>>(A);
    zgemm_mma_kernel<<<M_TOT / 64, 256, ZSMEM>>>();
    mgemm_mma_kernel<<<dim3(O_DIM / 128, M_TOT / 128), 256, MSMEM>>>(bias, out);
}